// round 12
// baseline (speedup 1.0000x reference)
#include <cuda_runtime.h>
#include <cuda_fp16.h>

#define ELEMF 64
#define NBRF  32
#define COUT  128
#define KTOT  160
#define EPS   1e-5f
#define E_MAX 1600000
#define N_MAX 50000

// pgemm tiles use the proven 336B row stride; egemm uses 80B (64B data + pad,
// banks r*20 mod 32 all distinct -> conflict-free LDSM)
#define RS336 336
#define RS80  80
#define MTILE 128
#define EATILE (MTILE * RS80)           // 10240 (edge A tile)
#define EBTILE (128 * RS80)             // 10240 (W3 B tile)
#define STAGE_STRIDE 80
#define STAGE_WARP (32 * STAGE_STRIDE)  // 2560 B/warp, 16 warps = 40960

// ---------------- scratch (device globals; no allocation allowed) -----------
__device__ __half g_hidden2[(size_t)E_MAX * COUT]; // pre-BN1 hidden (E,128) fp16
__device__ float g_sums[(size_t)N_MAX * ELEMF];
__device__ float g_stats1[2 * COUT];
__device__ float g_stats2[2 * ELEMF];
__device__ __half g_edgeF[(size_t)E_MAX * NBRF];          // edge features fp16
__device__ unsigned char g_W12[256 * RS336];              // W rows 0..127 -> [n][k] k=64, two tables stacked (n<128: W[0:64]; n>=128: W[64:128])
__device__ unsigned char g_W3f[128 * RS80];               // W rows 128..159 -> [n][k] k=32
__device__ __half g_P12[(size_t)N_MAX * 256];             // per-atom partials: [i][0:128]=P1, [i][128:256]=P2

// ---------------- helpers -----------------------------------------------------
__device__ __forceinline__ unsigned smem_u32(const void* p) {
    unsigned a;
    asm("{ .reg .u64 t; cvta.to.shared.u64 t, %1; cvt.u32.u64 %0, t; }"
        : "=r"(a) : "l"(p));
    return a;
}
__device__ __forceinline__ void ldsm4(unsigned addr, unsigned& r0, unsigned& r1,
                                      unsigned& r2, unsigned& r3) {
    asm volatile("ldmatrix.sync.aligned.m8n8.x4.shared.b16 {%0,%1,%2,%3}, [%4];"
                 : "=r"(r0), "=r"(r1), "=r"(r2), "=r"(r3) : "r"(addr));
}
__device__ __forceinline__ void mma16816(float* d, const unsigned* a,
                                         unsigned b0, unsigned b1) {
    asm volatile("mma.sync.aligned.m16n8k16.row.col.f32.f16.f16.f32 "
                 "{%0,%1,%2,%3}, {%4,%5,%6,%7}, {%8,%9}, {%0,%1,%2,%3};"
                 : "+f"(d[0]), "+f"(d[1]), "+f"(d[2]), "+f"(d[3])
                 : "r"(a[0]), "r"(a[1]), "r"(a[2]), "r"(a[3]), "r"(b0), "r"(b1));
}
__device__ __forceinline__ void cp16cg(unsigned dst, const void* src) {
    asm volatile("cp.async.cg.shared.global [%0], [%1], 16;"
                 :: "r"(dst), "l"(src) : "memory");
}
#define CP_COMMIT() asm volatile("cp.async.commit_group;" ::: "memory")
#define CP_WAIT(n)  asm volatile("cp.async.wait_group %0;" :: "n"(n) : "memory")
__device__ __forceinline__ unsigned h2pack(float a, float b) {
    __half2 p = __floats2half2_rn(a, b);
    return *reinterpret_cast<unsigned*>(&p);
}

// ---------------- kernels ----------------------------------------------------
// launch 0
__global__ void zero_kernel(int n_sums) {
    int i = blockIdx.x * blockDim.x + threadIdx.x;
    int stride = gridDim.x * blockDim.x;
    for (int j = i; j < n_sums; j += stride) g_sums[j] = 0.f;
    if (i < 2 * COUT)  g_stats1[i] = 0.f;
    if (i < 2 * ELEMF) g_stats2[i] = 0.f;
}

// launch 1: edge features fp32->fp16 + both W images
__global__ void prep_kernel(const float* __restrict__ W,
                            const float* __restrict__ nbrfea, int nEdge) {
    int i = blockIdx.x * blockDim.x + threadIdx.x;
    if (i < nEdge) g_edgeF[i] = __float2half_rn(nbrfea[i]);
    if (i < 16384) {            // W12: [256 n][64 k]
        int n = i >> 6, k = i & 63;
        float w = (n < 128) ? W[k * COUT + n] : W[(64 + k) * COUT + (n - 128)];
        *reinterpret_cast<__half*>(g_W12 + n * RS336 + k * 2) = __float2half_rn(w);
    } else if (i < 20480) {     // W3: [128 n][32 k]
        int i2 = i - 16384;
        int n = i2 >> 5, k = i2 & 31;
        *reinterpret_cast<__half*>(g_W3f + n * RS80 + k * 2) =
            __float2half_rn(W[(128 + k) * COUT + n]);
    }
}

// launch 2: P-GEMM: P12[i] = [atom[i] @ W[0:64] | atom[i] @ W[64:128]]  (N x 256)
// 512 threads, 16 warps = 2m(x64) x 8n(x32); M=128 tile, K=64 (4 k-steps), N=256.
__global__ __launch_bounds__(512, 1) void pgemm_kernel(
    const float* __restrict__ atom, int Nn)
{
    extern __shared__ char smem[];
    const unsigned sbase = smem_u32(smem);
    const int A_OFF = 0;            // 128 x 336 = 43008
    const int B_OFF = 43008;        // 256 x 336 = 86016

    const int tid = threadIdx.x, wid = tid >> 5, lane = tid & 31;

    {
        const uint4* src = reinterpret_cast<const uint4*>(g_W12);
        uint4* dst = reinterpret_cast<uint4*>(smem + B_OFF);
        for (int i = tid; i < 256 * RS336 / 16; i += 512) dst[i] = src[i];
    }
    // A: convert atom rows fp32->fp16
    {
        const int row = tid >> 2, q = tid & 3;
        const int gi = blockIdx.x * 128 + row;
        const float4 Z = make_float4(0.f, 0.f, 0.f, 0.f);
        const float4* src = reinterpret_cast<const float4*>(atom + (size_t)gi * ELEMF + q * 16);
        float4 v0 = (gi < Nn) ? src[0] : Z;
        float4 v1 = (gi < Nn) ? src[1] : Z;
        float4 v2 = (gi < Nn) ? src[2] : Z;
        float4 v3 = (gi < Nn) ? src[3] : Z;
        uint4 o0, o1;
        o0.x = h2pack(v0.x, v0.y); o0.y = h2pack(v0.z, v0.w);
        o0.z = h2pack(v1.x, v1.y); o0.w = h2pack(v1.z, v1.w);
        o1.x = h2pack(v2.x, v2.y); o1.y = h2pack(v2.z, v2.w);
        o1.z = h2pack(v3.x, v3.y); o1.w = h2pack(v3.z, v3.w);
        *reinterpret_cast<uint4*>(smem + A_OFF + row * RS336 + q * 32)      = o0;
        *reinterpret_cast<uint4*>(smem + A_OFF + row * RS336 + q * 32 + 16) = o1;
    }
    __syncthreads();

    const int wm = (wid >> 3) * 64;             // 2 m-warps
    const int wn = (wid & 7) * 32;              // 8 n-warps -> N=256
    const unsigned lane_off = (lane & 15) * RS336 + ((lane >> 4) << 4);
    const unsigned abase = sbase + A_OFF + wm * RS336 + lane_off;
    const unsigned bbase = sbase + B_OFF + wn * RS336 + lane_off;

    float d[4][4][4];
#pragma unroll
    for (int i = 0; i < 4; ++i)
#pragma unroll
        for (int j = 0; j < 4; ++j)
#pragma unroll
            for (int q2 = 0; q2 < 4; ++q2) d[i][j][q2] = 0.f;

#pragma unroll
    for (int kk = 0; kk < 4; ++kk) {
        const unsigned kb = kk * 32;
        unsigned a[4][4];
#pragma unroll
        for (int i = 0; i < 4; ++i)
            ldsm4(abase + i * 16 * RS336 + kb, a[i][0], a[i][1], a[i][2], a[i][3]);
        unsigned u0, u1, u2, u3, w0, w1, w2, w3;
        ldsm4(bbase + kb,               u0, u1, u2, u3);
        ldsm4(bbase + 16 * RS336 + kb,  w0, w1, w2, w3);
#pragma unroll
        for (int i = 0; i < 4; ++i) {
            mma16816(d[i][0], a[i], u0, u2);
            mma16816(d[i][1], a[i], u1, u3);
            mma16816(d[i][2], a[i], w0, w2);
            mma16816(d[i][3], a[i], w1, w3);
        }
    }

    const int cb = wn + 2 * (lane & 3);
#pragma unroll
    for (int i = 0; i < 4; ++i) {
        const int g1 = blockIdx.x * 128 + wm + 16 * i + (lane >> 2);
        const int g2 = g1 + 8;
#pragma unroll
        for (int j = 0; j < 4; ++j) {
            if (g1 < Nn)
                *reinterpret_cast<__half2*>(g_P12 + (size_t)g1 * 256 + cb + 8 * j) =
                    __floats2half2_rn(d[i][j][0], d[i][j][1]);
            if (g2 < Nn)
                *reinterpret_cast<__half2*>(g_P12 + (size_t)g2 * 256 + cb + 8 * j) =
                    __floats2half2_rn(d[i][j][2], d[i][j][3]);
        }
    }
}

// launch 3 (ncu target): edge GEMM (E x 32 @ 32 x 128) + P1/P2 gather-add epilogue.
// Persistent, 512 threads (4m x 4n warps, warp tile m32 x n32), M=128 tiles,
// double-buffered edge A via cp.async, B fragments hoisted into registers,
// hidden store via staged coalesced STG.128.
__global__ __launch_bounds__(512, 1) void egemm_kernel(
    const int* __restrict__ selfIdx, const int* __restrict__ nbrIdx,
    const float* __restrict__ bias, int E, int nTiles)
{
    extern __shared__ char smem[];
    const unsigned sbase = smem_u32(smem);
    const int B_OFF    = 2 * EATILE;            // 20480
    const int BIAS_OFF = B_OFF + EBTILE;        // 30720
    const int STAT_OFF = BIAS_OFF + 512;        // 31232
    const int STAGE_OFF = STAT_OFF + 1024;      // 32256

    const int tid = threadIdx.x, wid = tid >> 5, lane = tid & 31;

    {
        const uint4* src = reinterpret_cast<const uint4*>(g_W3f);
        uint4* dst = reinterpret_cast<uint4*>(smem + B_OFF);
        for (int i = tid; i < EBTILE / 16; i += 512) dst[i] = src[i];
    }
    if (tid < COUT) reinterpret_cast<float*>(smem + BIAS_OFF)[tid] = bias[tid];
    if (tid < 256)  reinterpret_cast<float*>(smem + STAT_OFF)[tid] = 0.f;
    __syncthreads();

    const int wm = (wid >> 2) * 32;             // 4 m-warps -> M=128
    const int wn = (wid & 3) * 32;              // 4 n-warps -> N=128
    const unsigned lane_off = (lane & 15) * RS80 + ((lane >> 4) << 4);
    const int cb = wn + 2 * (lane & 3);
    const float* sbias = reinterpret_cast<const float*>(smem + BIAS_OFF);
    float* sstat = reinterpret_cast<float*>(smem + STAT_OFF);

    // hoist B fragments (K=32 -> 2 k-steps x 8 regs)
    unsigned bu[2][4], bw[2][4];
    {
        const unsigned bbase = sbase + B_OFF + wn * RS80 + lane_off;
#pragma unroll
        for (int kk = 0; kk < 2; ++kk) {
            ldsm4(bbase + kk * 32,              bu[kk][0], bu[kk][1], bu[kk][2], bu[kk][3]);
            ldsm4(bbase + 16 * RS80 + kk * 32,  bw[kk][0], bw[kk][1], bw[kk][2], bw[kk][3]);
        }
    }

    const int gr = tid >> 2, gq = tid & 3;      // 4 threads/row, 1 cp.async each

    float aS0[4] = {0,0,0,0}, aS1[4] = {0,0,0,0};
    float aQ0[4] = {0,0,0,0}, aQ1[4] = {0,0,0,0};

    int tile = blockIdx.x;
    if (tile < nTiles) {
        const int e = tile * MTILE + gr;
        if (e < E)
            cp16cg(sbase + gr * RS80 + gq * 16, g_edgeF + (size_t)e * NBRF + gq * 8);
    }
    CP_COMMIT();

    int buf = 0;
    for (; tile < nTiles; tile += gridDim.x) {
        const int eb = tile * MTILE;
        const int next = tile + gridDim.x;

        if (next < nTiles) {
            const int e = next * MTILE + gr;
            if (e < E)
                cp16cg(sbase + (buf ^ 1) * EATILE + gr * RS80 + gq * 16,
                       g_edgeF + (size_t)e * NBRF + gq * 8);
            CP_COMMIT();
            CP_WAIT(1);
        } else {
            CP_WAIT(0);
        }
        __syncthreads();   // buf visible

        const unsigned abase = sbase + buf * EATILE + wm * RS80 + lane_off;
        float d[2][4][4];
#pragma unroll
        for (int i = 0; i < 2; ++i)
#pragma unroll
            for (int j = 0; j < 4; ++j)
#pragma unroll
                for (int q2 = 0; q2 < 4; ++q2) d[i][j][q2] = 0.f;

#pragma unroll
        for (int kk = 0; kk < 2; ++kk) {
            const unsigned kb = kk * 32;
            unsigned a[2][4];
            ldsm4(abase + kb,             a[0][0], a[0][1], a[0][2], a[0][3]);
            ldsm4(abase + 16 * RS80 + kb, a[1][0], a[1][1], a[1][2], a[1][3]);
#pragma unroll
            for (int i = 0; i < 2; ++i) {
                mma16816(d[i][0], a[i], bu[kk][0], bu[kk][2]);
                mma16816(d[i][1], a[i], bu[kk][1], bu[kk][3]);
                mma16816(d[i][2], a[i], bw[kk][0], bw[kk][2]);
                mma16816(d[i][3], a[i], bw[kk][1], bw[kk][3]);
            }
        }

        // ---- epilogue: P1/P2 gather-add + bias + stats (fragment layout),
        //      then staged coalesced store ----
        {
            const unsigned stg = sbase + STAGE_OFF + wid * STAGE_WARP;
            const int rlane = lane >> 2;
            const int hidx = (cb >> 1);   // half2 index base within 128-col row
#pragma unroll
            for (int i = 0; i < 2; ++i) {
                const int e1 = eb + wm + 16 * i + rlane;
                const int e2 = e1 + 8;
                const bool v1 = (e1 < E), v2 = (e2 < E);
                const int s1 = v1 ? selfIdx[e1] : 0;
                const int n1 = v1 ? nbrIdx[e1]  : 0;
                const int s2 = v2 ? selfIdx[e2] : 0;
                const int n2 = v2 ? nbrIdx[e2]  : 0;
                const __half2* P1a = reinterpret_cast<const __half2*>(g_P12 + (size_t)s1 * 256);
                const __half2* P2a = reinterpret_cast<const __half2*>(g_P12 + (size_t)n1 * 256 + 128);
                const __half2* P1b = reinterpret_cast<const __half2*>(g_P12 + (size_t)s2 * 256);
                const __half2* P2b = reinterpret_cast<const __half2*>(g_P12 + (size_t)n2 * 256 + 128);
                const unsigned r1off = stg + (16 * i + rlane) * STAGE_STRIDE + 4 * (lane & 3);
                const unsigned r2off = r1off + 8 * STAGE_STRIDE;
#pragma unroll
                for (int j = 0; j < 4; ++j) {
                    const float b0 = sbias[cb + 8 * j];
                    const float b1 = sbias[cb + 8 * j + 1];
                    const int hj = hidx + 4 * j;
                    float v00 = d[i][j][0] + b0;
                    float v01 = d[i][j][1] + b1;
                    float v10 = d[i][j][2] + b0;
                    float v11 = d[i][j][3] + b1;
                    if (v1) {
                        const __half2 p1 = P1a[hj], p2 = P2a[hj];
                        v00 += __low2float(p1) + __low2float(p2);
                        v01 += __high2float(p1) + __high2float(p2);
                        aS0[j] += v00; aS1[j] += v01;
                        aQ0[j] += v00 * v00; aQ1[j] += v01 * v01;
                    }
                    if (v2) {
                        const __half2 p1 = P1b[hj], p2 = P2b[hj];
                        v10 += __low2float(p1) + __low2float(p2);
                        v11 += __high2float(p1) + __high2float(p2);
                        aS0[j] += v10; aS1[j] += v11;
                        aQ0[j] += v10 * v10; aQ1[j] += v11 * v11;
                    }
                    __half2 h1 = __floats2half2_rn(v00, v01);
                    __half2 h2 = __floats2half2_rn(v10, v11);
                    asm volatile("st.shared.b32 [%0], %1;"
                                 :: "r"(r1off + 16 * j),
                                    "r"(*reinterpret_cast<unsigned*>(&h1)) : "memory");
                    asm volatile("st.shared.b32 [%0], %1;"
                                 :: "r"(r2off + 16 * j),
                                    "r"(*reinterpret_cast<unsigned*>(&h2)) : "memory");
                }
            }
            __syncwarp();
#pragma unroll
            for (int c = 0; c < 4; ++c) {
                const int q = 32 * c + lane;
                const int rl = q >> 2, cq = q & 3;
                const int er = eb + wm + rl;
                if (er < E) {
                    uint4 val;
                    asm volatile("ld.shared.v4.b32 {%0,%1,%2,%3}, [%4];"
                                 : "=r"(val.x), "=r"(val.y), "=r"(val.z), "=r"(val.w)
                                 : "r"(stg + rl * STAGE_STRIDE + cq * 16));
                    *reinterpret_cast<uint4*>(g_hidden2 + (size_t)er * COUT + wn + cq * 8) = val;
                }
            }
        }
        __syncthreads();   // LDSM on buf done before next cp.async recycles it
        buf ^= 1;
    }

#pragma unroll
    for (int j = 0; j < 4; ++j) {
#pragma unroll
        for (int ofs = 4; ofs <= 16; ofs <<= 1) {
            aS0[j] += __shfl_xor_sync(0xFFFFFFFF, aS0[j], ofs);
            aS1[j] += __shfl_xor_sync(0xFFFFFFFF, aS1[j], ofs);
            aQ0[j] += __shfl_xor_sync(0xFFFFFFFF, aQ0[j], ofs);
            aQ1[j] += __shfl_xor_sync(0xFFFFFFFF, aQ1[j], ofs);
        }
        if (lane < 4) {
            const int c = wn + 2 * lane + 8 * j;
            atomicAdd(&sstat[c], aS0[j]);
            atomicAdd(&sstat[c + 1], aS1[j]);
            atomicAdd(&sstat[COUT + c], aQ0[j]);
            atomicAdd(&sstat[COUT + c + 1], aQ1[j]);
        }
    }
    __syncthreads();
    if (tid < 256) atomicAdd(&g_stats1[tid], sstat[tid]);
}

// launch 4: BN1 apply + gate + segment-sum, f16x2 math, fp32 accumulation.
__global__ __launch_bounds__(256) void msg_segsum_kernel(
    const int* __restrict__ selfIdx,
    const float* __restrict__ gamma1, const float* __restrict__ beta1,
    int E, float invE)
{
    __shared__ float s1[128], t1[128];
    const int tid = threadIdx.x;
    if (tid < 128) {
        float mean = g_stats1[tid] * invE;
        float var  = g_stats1[128 + tid] * invE - mean * mean;
        float r = rsqrtf(var + EPS);
        float g = gamma1[tid];
        s1[tid] = g * r;
        t1[tid] = beta1[tid] - g * mean * r;
    }
    __syncthreads();

    const int p = tid & 31;
    const int chunk = tid >> 5;
    const int CHUNK = 64;
    long gl = (long)blockIdx.x * 8 + chunk;
    int es = (int)(gl * CHUNK);
    if (es >= E) return;
    int ee = min(es + CHUNK, E);

    const __half2 sf2 = __floats2half2_rn(s1[2*p],      s1[2*p + 1]);
    const __half2 tf2 = __floats2half2_rn(t1[2*p],      t1[2*p + 1]);
    const __half2 sc2 = __floats2half2_rn(s1[64 + 2*p], s1[64 + 2*p + 1]);
    const __half2 tc2 = __floats2half2_rn(t1[64 + 2*p], t1[64 + 2*p + 1]);
    const __half2 one2  = __floats2half2_rn(1.f, 1.f);
    const __half2 zero2 = __floats2half2_rn(0.f, 0.f);

    int cur = selfIdx[es];
    float acc0 = 0.f, acc1 = 0.f;
    for (int e = es; e < ee; ++e) {
        int a = selfIdx[e];
        if (a != cur) {
            atomicAdd(&g_sums[(size_t)cur * ELEMF + 2*p],     acc0);
            atomicAdd(&g_sums[(size_t)cur * ELEMF + 2*p + 1], acc1);
            cur = a; acc0 = 0.f; acc1 = 0.f;
        }
        const __half2* hp = reinterpret_cast<const __half2*>(g_hidden2 + (size_t)e * COUT);
        __half2 f = __hfma2(sf2, hp[p], tf2);
        __half2 g = __hfma2(sc2, hp[32 + p], tc2);
        __half2 sig = h2rcp(__hadd2(one2, h2exp(__hneg2(f))));
        __half2 sp  = __hadd2(__hmax2(g, zero2),
                              h2log(__hadd2(one2, h2exp(__hneg2(__habs2(g))))));
        float2 m = __half22float2(__hmul2(sig, sp));
        acc0 += m.x; acc1 += m.y;
    }
    atomicAdd(&g_sums[(size_t)cur * ELEMF + 2*p],     acc0);
    atomicAdd(&g_sums[(size_t)cur * ELEMF + 2*p + 1], acc1);
}

// launch 5
__global__ __launch_bounds__(256) void stats2_kernel(int Nn) {
    __shared__ float rs[4][64];
    __shared__ float rq[4][64];
    const int tid = threadIdx.x;
    const int c = tid & 63, rl = tid >> 6;
    float s = 0.f, q = 0.f;
    for (int row = blockIdx.x * 4 + rl; row < Nn; row += gridDim.x * 4) {
        float v = g_sums[(size_t)row * ELEMF + c];
        s += v; q += v * v;
    }
    rs[rl][c] = s; rq[rl][c] = q;
    __syncthreads();
    if (tid < 64) {
        float ss = 0.f, qq = 0.f;
#pragma unroll
        for (int r = 0; r < 4; ++r) { ss += rs[r][tid]; qq += rq[r][tid]; }
        atomicAdd(&g_stats2[tid], ss);
        atomicAdd(&g_stats2[64 + tid], qq);
    }
}

// launch 6
__device__ __forceinline__ float softplusf(float x) {
    return (x > 15.f) ? x : log1pf(expf(x));
}
__global__ __launch_bounds__(256) void out_kernel(
    const float* __restrict__ atom,
    const float* __restrict__ gamma2, const float* __restrict__ beta2,
    float* __restrict__ outp, int Nn, float invN)
{
    __shared__ float s2[64], t2[64];
    const int tid = threadIdx.x;
    if (tid < 64) {
        float mean = g_stats2[tid] * invN;
        float var  = g_stats2[64 + tid] * invN - mean * mean;
        float r = rsqrtf(var + EPS);
        float g = gamma2[tid];
        s2[tid] = g * r;
        t2[tid] = beta2[tid] - g * mean * r;
    }
    __syncthreads();
    const int c = tid & 63, rl = tid >> 6;
    for (int row = blockIdx.x * 4 + rl; row < Nn; row += gridDim.x * 4) {
        size_t idx = (size_t)row * ELEMF + c;
        float v = fmaf(s2[c], g_sums[idx], t2[c]) + atom[idx];
        outp[idx] = softplusf(v);
    }
}

extern "C" void kernel_launch(void* const* d_in, const int* in_sizes, int n_in,
                              void* d_out, int out_size)
{
    const float* atom   = (const float*)d_in[0];
    const float* nbrfea = (const float*)d_in[1];
    const int*   sIdx   = (const int*)d_in[2];
    const int*   nIdx   = (const int*)d_in[3];
    const float* W      = (const float*)d_in[4];
    const float* b      = (const float*)d_in[5];
    const float* gamma1 = (const float*)d_in[6];
    const float* beta1  = (const float*)d_in[7];
    const float* gamma2 = (const float*)d_in[8];
    const float* beta2  = (const float*)d_in[9];
    float* outp = (float*)d_out;

    const int Nn = in_sizes[0] / ELEMF;
    const int E  = in_sizes[2];
    const int nTiles = (E + MTILE - 1) / MTILE;
    const int nEdge = E * NBRF;

    const int PG_SMEM = 43008 + 86016;                    // 129024
    const int EG_SMEM = 2 * EATILE + EBTILE + 512 + 1024 + 16 * STAGE_WARP; // 73216
    cudaFuncSetAttribute(pgemm_kernel,
                         cudaFuncAttributeMaxDynamicSharedMemorySize, PG_SMEM);
    cudaFuncSetAttribute(egemm_kernel,
                         cudaFuncAttributeMaxDynamicSharedMemorySize, EG_SMEM);
    int sms = 148;
    cudaDeviceGetAttribute(&sms, cudaDevAttrMultiProcessorCount, 0);
    int grid = sms < nTiles ? sms : nTiles;

    zero_kernel<<<2048, 256>>>(Nn * ELEMF);
    prep_kernel<<<(nEdge + 255) / 256, 256>>>(W, nbrfea, nEdge);
    pgemm_kernel<<<(Nn + 127) / 128, 512, PG_SMEM>>>(atom, Nn);
    egemm_kernel<<<grid, 512, EG_SMEM>>>(sIdx, nIdx, b, E, nTiles);

    int msg_blocks = (E + 8 * 64 - 1) / (8 * 64);
    msg_segsum_kernel<<<msg_blocks, 256>>>(sIdx, gamma1, beta1, E, 1.f / (float)E);

    stats2_kernel<<<592, 256>>>(Nn);

    int out_blocks = (Nn + 3) / 4;
    out_kernel<<<out_blocks, 256>>>(atom, gamma2, beta2, outp, Nn, 1.f / (float)Nn);
}